// round 5
// baseline (speedup 1.0000x reference)
#include <cuda_runtime.h>
#include <cuda_bf16.h>
#include <math.h>

#define LSEQ 4096
#define HDIM 2048
#define HKN  16
#define HVN  32
#define KEY_DIM  2048
#define VAL_DIM  4096
#define CONV_DIM 8192
#define NPROJ    12352
#define QKVZ_DIM 12288
#define EPSF 1e-6f

// ---------------- scratch (device globals; no runtime allocation) ------------
__device__ float g_proj [LSEQ * (size_t)NPROJ];
__device__ float g_mixed[LSEQ * (size_t)CONV_DIM];
__device__ float g_qn   [LSEQ * (size_t)KEY_DIM];
__device__ float g_kn   [LSEQ * (size_t)KEY_DIM];
__device__ float g_g    [LSEQ * HVN];
__device__ float g_beta [LSEQ * HVN];
__device__ float g_core [LSEQ * (size_t)VAL_DIM];

__device__ __nv_bfloat16 g_hs_hi [LSEQ * (size_t)HDIM];
__device__ __nv_bfloat16 g_hs_lo [LSEQ * (size_t)HDIM];
__device__ __nv_bfloat16 g_win_hi[(size_t)HDIM * NPROJ];
__device__ __nv_bfloat16 g_win_lo[(size_t)HDIM * NPROJ];
__device__ __nv_bfloat16 g_wout_hi[(size_t)VAL_DIM * HDIM];
__device__ __nv_bfloat16 g_wout_lo[(size_t)VAL_DIM * HDIM];
__device__ __nv_bfloat16 g_y_hi [LSEQ * (size_t)VAL_DIM];
__device__ __nv_bfloat16 g_y_lo [LSEQ * (size_t)VAL_DIM];

// ---------------- helpers ----------------------------------------------------
__device__ __forceinline__ unsigned sptr(const void* p) {
    return (unsigned)__cvta_generic_to_shared(p);
}
__device__ __forceinline__ void ldsm4(unsigned &r0, unsigned &r1, unsigned &r2, unsigned &r3, unsigned a) {
    asm volatile("ldmatrix.sync.aligned.m8n8.x4.shared.b16 {%0,%1,%2,%3},[%4];"
                 : "=r"(r0), "=r"(r1), "=r"(r2), "=r"(r3) : "r"(a));
}
__device__ __forceinline__ void ldsm4t(unsigned &r0, unsigned &r1, unsigned &r2, unsigned &r3, unsigned a) {
    asm volatile("ldmatrix.sync.aligned.m8n8.x4.trans.shared.b16 {%0,%1,%2,%3},[%4];"
                 : "=r"(r0), "=r"(r1), "=r"(r2), "=r"(r3) : "r"(a));
}
__device__ __forceinline__ void mma_bf16(float* c, const unsigned* a, const unsigned* b) {
    asm volatile("mma.sync.aligned.m16n8k16.row.col.f32.bf16.bf16.f32 "
                 "{%0,%1,%2,%3},{%4,%5,%6,%7},{%8,%9},{%0,%1,%2,%3};"
                 : "+f"(c[0]), "+f"(c[1]), "+f"(c[2]), "+f"(c[3])
                 : "r"(a[0]), "r"(a[1]), "r"(a[2]), "r"(a[3]), "r"(b[0]), "r"(b[1]));
}
__device__ __forceinline__ void cpa16(unsigned d, const void* s, int sz) {
    asm volatile("cp.async.cg.shared.global [%0],[%1],16,%2;" :: "r"(d), "l"(s), "r"(sz));
}

// ---------------- fp32 -> (bf16 hi, bf16 lo) split ---------------------------
__global__ void split_kernel(const float4* __restrict__ x,
                             __nv_bfloat16* __restrict__ hi,
                             __nv_bfloat16* __restrict__ lo, int n4)
{
    int i = blockIdx.x * blockDim.x + threadIdx.x;
    if (i >= n4) return;
    float4 v = x[i];
    float f[4] = {v.x, v.y, v.z, v.w};
    __nv_bfloat16 h[4], l[4];
#pragma unroll
    for (int j = 0; j < 4; j++) {
        h[j] = __float2bfloat16(f[j]);
        l[j] = __float2bfloat16(f[j] - __bfloat162float(h[j]));
    }
    ((__nv_bfloat162*)hi)[2*i]   = __nv_bfloat162(h[0], h[1]);
    ((__nv_bfloat162*)hi)[2*i+1] = __nv_bfloat162(h[2], h[3]);
    ((__nv_bfloat162*)lo)[2*i]   = __nv_bfloat162(l[0], l[1]);
    ((__nv_bfloat162*)lo)[2*i+1] = __nv_bfloat162(l[2], l[3]);
}

// ---------------- bf16-split tensor-core GEMM (mma.sync, 3-stage) ------------
// C[M,N] = (Ahi+Alo)[M,K] @ (Bhi+Blo)[K,N], fp32 acc, 3 passes.
// BM=128, BN=128, BK=32, 256 threads, 2 CTAs/SM, 3-stage cp.async pipeline,
// single __syncthreads per K-tile.
#define BM 128
#define BN 128
#define BK 32
#define A_ST 40
#define B_ST 136
#define A_TILE (BM * A_ST)            // 5120 halves
#define B_TILE (BK * B_ST)            // 4352 halves
#define STG_H  (2 * A_TILE + 2 * B_TILE)   // 18944 halves per stage
#define GEMM_SMEM (3 * STG_H * 2)          // 113664 bytes

__global__ __launch_bounds__(256, 2) void hgemm_split(
    const __nv_bfloat16* __restrict__ Ahi, const __nv_bfloat16* __restrict__ Alo,
    const __nv_bfloat16* __restrict__ Bhi, const __nv_bfloat16* __restrict__ Blo,
    float* __restrict__ C, int M, int N, int K)
{
    extern __shared__ __nv_bfloat16 sm[];

    const int tid  = threadIdx.x;
    const int lane = tid & 31;
    const int wid  = tid >> 5;
    const int wm   = (wid & 1) * 64;
    const int wn   = (wid >> 1) * 32;

    const int rowBase = blockIdx.y * BM;
    const int colBase = blockIdx.x * BN;

    float acc[4][4][4];
#pragma unroll
    for (int a = 0; a < 4; a++)
#pragma unroll
        for (int b = 0; b < 4; b++)
#pragma unroll
            for (int c = 0; c < 4; c++) acc[a][b][c] = 0.f;

    const int numTiles = K / BK;

    auto issue_tile = [&](int t) {
        const int k0 = t * BK;
        __nv_bfloat16* stg = sm + (t % 3) * STG_H;
        __nv_bfloat16* tAh = stg;
        __nv_bfloat16* tAl = stg + A_TILE;
        __nv_bfloat16* tBh = stg + 2 * A_TILE;
        __nv_bfloat16* tBl = stg + 2 * A_TILE + B_TILE;
#pragma unroll
        for (int i = 0; i < 2; i++) {
            int c  = tid + i * 256;
            int r  = c >> 2;
            int kc = (c & 3) * 8;
            size_t goff = (size_t)(rowBase + r) * K + k0 + kc;
            int soff = r * A_ST + kc;
            cpa16(sptr(tAh + soff), Ahi + goff, 16);
            cpa16(sptr(tAl + soff), Alo + goff, 16);
        }
#pragma unroll
        for (int i = 0; i < 2; i++) {
            int c  = tid + i * 256;
            int r  = c >> 4;
            int nc = (c & 15) * 8;
            int col = colBase + nc;
            int sz  = (col < N) ? 16 : 0;
            size_t goff = sz ? ((size_t)(k0 + r) * N + col) : 0;
            int soff = r * B_ST + nc;
            cpa16(sptr(tBh + soff), Bhi + goff, sz);
            cpa16(sptr(tBl + soff), Blo + goff, sz);
        }
        asm volatile("cp.async.commit_group;");
    };

    issue_tile(0);
    issue_tile(1);

    for (int t = 0; t < numTiles; t++) {
        asm volatile("cp.async.wait_group 1;");
        __syncthreads();
        if (t + 2 < numTiles) issue_tile(t + 2);
        else                  asm volatile("cp.async.commit_group;");

        __nv_bfloat16* stg = sm + (t % 3) * STG_H;
        const __nv_bfloat16* pAh = stg;
        const __nv_bfloat16* pAl = stg + A_TILE;
        const __nv_bfloat16* pBh = stg + 2 * A_TILE;
        const __nv_bfloat16* pBl = stg + 2 * A_TILE + B_TILE;

#pragma unroll
        for (int ks = 0; ks < 2; ks++) {
            unsigned ah[4][4], al[4][4], bh[4][2], bl[4][2];
            const int ar = lane & 15;
            const int ac = ks * 16 + (lane >> 4) * 8;
#pragma unroll
            for (int mt = 0; mt < 4; mt++) {
                unsigned ad = sptr(pAh + (wm + mt * 16 + ar) * A_ST + ac);
                ldsm4(ah[mt][0], ah[mt][1], ah[mt][2], ah[mt][3], ad);
                unsigned ad2 = sptr(pAl + (wm + mt * 16 + ar) * A_ST + ac);
                ldsm4(al[mt][0], al[mt][1], al[mt][2], al[mt][3], ad2);
            }
            const int brow = ks * 16 + (lane & 7) + ((lane & 8) ? 8 : 0);
            const int bcsel = ((lane >> 4) & 1) * 8;
#pragma unroll
            for (int pr = 0; pr < 2; pr++) {
                int bc = wn + pr * 16 + bcsel;
                unsigned bd = sptr(pBh + brow * B_ST + bc);
                ldsm4t(bh[pr*2][0], bh[pr*2][1], bh[pr*2+1][0], bh[pr*2+1][1], bd);
                unsigned bd2 = sptr(pBl + brow * B_ST + bc);
                ldsm4t(bl[pr*2][0], bl[pr*2][1], bl[pr*2+1][0], bl[pr*2+1][1], bd2);
            }
#pragma unroll
            for (int mt = 0; mt < 4; mt++)
#pragma unroll
                for (int nt = 0; nt < 4; nt++) {
                    mma_bf16(acc[mt][nt], ah[mt], bh[nt]);
                    mma_bf16(acc[mt][nt], ah[mt], bl[nt]);
                    mma_bf16(acc[mt][nt], al[mt], bh[nt]);
                }
        }
    }

#pragma unroll
    for (int mt = 0; mt < 4; mt++)
#pragma unroll
        for (int nt = 0; nt < 4; nt++) {
            int row = rowBase + wm + mt * 16 + (lane >> 2);
            int col = colBase + wn + nt * 8 + (lane & 3) * 2;
            if (col < N) {
                float2 v0 = make_float2(acc[mt][nt][0], acc[mt][nt][1]);
                float2 v1 = make_float2(acc[mt][nt][2], acc[mt][nt][3]);
                *(float2*)(C + (size_t)row * N + col)       = v0;
                *(float2*)(C + (size_t)(row + 8) * N + col) = v1;
            }
        }
}

// ---------------- causal conv(K=4) + SiLU ------------------------------------
__global__ void conv_silu_kernel(const float* __restrict__ conv_w)
{
    const int idx = blockIdx.x * blockDim.x + threadIdx.x;
    if (idx >= LSEQ * CONV_DIM) return;
    const int t = idx / CONV_DIM;
    const int c = idx - t * CONV_DIM;

    int col;
    if (c < KEY_DIM) {
        col = (c >> 7) * 768 + (c & 127);
    } else if (c < 2 * KEY_DIM) {
        const int cc = c - KEY_DIM;
        col = (cc >> 7) * 768 + 128 + (cc & 127);
    } else {
        const int cc = c - 2 * KEY_DIM;
        col = (cc >> 8) * 768 + 256 + (cc & 255);
    }

    float accv = 0.f;
#pragma unroll
    for (int j = 0; j < 4; j++) {
        const int tt = t - 3 + j;
        if (tt >= 0)
            accv = fmaf(conv_w[c * 4 + j], g_proj[(size_t)tt * NPROJ + col], accv);
    }
    g_mixed[idx] = accv / (1.f + expf(-accv));
}

// ---------------- beta / g activations ---------------------------------------
__global__ void gb_kernel(const float* __restrict__ A_log,
                          const float* __restrict__ dt_bias)
{
    const int i = blockIdx.x * blockDim.x + threadIdx.x;
    if (i >= LSEQ * HVN) return;
    const int t  = i >> 5;
    const int hv = i & 31;
    const int hk = hv >> 1;
    const int gi = hv & 1;
    const float* row = g_proj + (size_t)t * NPROJ + QKVZ_DIM + hk * 4;
    const float b = row[gi];
    const float a = row[2 + gi];
    g_beta[i] = 1.f / (1.f + expf(-b));
    const float x  = a + dt_bias[hv];
    const float sp = (x > 20.f) ? x : log1pf(expf(x));
    g_g[i] = -expf(A_log[hv]) * sp;
}

// ---------------- q/k L2 normalization ---------------------------------------
__global__ __launch_bounds__(128) void qknorm_kernel()
{
    const int t = blockIdx.x;
    const int h = blockIdx.y;
    const int d = threadIdx.x;
    const bool isQ = h < HKN;
    const int hk = isQ ? h : h - HKN;

    const float v = g_mixed[(size_t)t * CONV_DIM + (isQ ? 0 : KEY_DIM) + hk * 128 + d];

    __shared__ float red[128];
    red[d] = v * v;
    __syncthreads();
    for (int s = 64; s > 0; s >>= 1) {
        if (d < s) red[d] += red[d + s];
        __syncthreads();
    }
    float scale = 1.f / sqrtf(red[0] + EPSF);
    if (isQ) scale *= 0.08838834764831845f;
    const float outv = v * scale;
    if (isQ) g_qn[(size_t)t * KEY_DIM + hk * 128 + d] = outv;
    else     g_kn[(size_t)t * KEY_DIM + hk * 128 + d] = outv;
}

// ---------------- gated delta recurrence (128 blocks, quad row-split) --------
__global__ __launch_bounds__(128, 1) void scan_kernel2()
{
    const int hv = blockIdx.x >> 2;
    const int cg = blockIdx.x & 3;
    const int tid = threadIdx.x;
    const int j  = tid >> 2;
    const int r  = tid & 3;
    const int col = cg * 32 + j;
    const int hk = hv >> 1;

    float S[32];
#pragma unroll
    for (int i = 0; i < 32; i++) S[i] = 0.f;

    __shared__ float2 skq[2][4 * 33];

    const float* kb = g_kn + hk * 128;
    const float* qb = g_qn + hk * 128;
    const float* vb = g_mixed + 2 * KEY_DIM + hv * 128 + col;
    const int sidx = (tid >> 5) * 33 + (tid & 31);

    float2 kq = make_float2(kb[tid], qb[tid]);
    float vv = vb[0];
    float gg = g_g[hv];
    float bb = g_beta[hv];
    skq[0][sidx] = kq;
    __syncthreads();

    for (int t = 0; t < LSEQ; t++) {
        const int buf = t & 1;
        float2 kq_n; float vv_n = 0.f, gg_n = 0.f, bb_n = 0.f;
        if (t + 1 < LSEQ) {
            kq_n = make_float2(kb[(size_t)(t + 1) * KEY_DIM + tid],
                               qb[(size_t)(t + 1) * KEY_DIM + tid]);
            vv_n = vb[(size_t)(t + 1) * CONV_DIM];
            gg_n = g_g[(t + 1) * HVN + hv];
            bb_n = g_beta[(t + 1) * HVN + hv];
        }

        const float eg = expf(gg);
        const float2* kqrow = &skq[buf][r * 33];

        float ks = 0.f;
#pragma unroll
        for (int i = 0; i < 32; i++) {
            S[i] *= eg;
            ks = fmaf(kqrow[i].x, S[i], ks);
        }
        ks += __shfl_xor_sync(0xffffffffu, ks, 1);
        ks += __shfl_xor_sync(0xffffffffu, ks, 2);
        const float delta = (vv - ks) * bb;

        float o = 0.f;
#pragma unroll
        for (int i = 0; i < 32; i++) {
            S[i] = fmaf(kqrow[i].x, delta, S[i]);
            o = fmaf(kqrow[i].y, S[i], o);
        }
        o += __shfl_xor_sync(0xffffffffu, o, 1);
        o += __shfl_xor_sync(0xffffffffu, o, 2);
        if (r == 0)
            g_core[(size_t)t * VAL_DIM + hv * 128 + col] = o;

        if (t + 1 < LSEQ) {
            skq[buf ^ 1][sidx] = kq_n;
            vv = vv_n; gg = gg_n; bb = bb_n;
        }
        __syncthreads();
    }
}

// ---------------- gated RMSNorm * silu(z), writes split bf16 -----------------
__global__ __launch_bounds__(128) void gated_norm_kernel(const float* __restrict__ norm_w)
{
    const int t  = blockIdx.x;
    const int hv = blockIdx.y;
    const int d  = threadIdx.x;
    const int hk = hv >> 1;
    const int gi = hv & 1;

    const float c = g_core[(size_t)t * VAL_DIM + hv * 128 + d];

    __shared__ float red[128];
    red[d] = c * c;
    __syncthreads();
    for (int s = 64; s > 0; s >>= 1) {
        if (d < s) red[d] += red[d + s];
        __syncthreads();
    }
    const float var = red[0] * (1.f / 128.f);

    const float z  = g_proj[(size_t)t * NPROJ + hk * 768 + 512 + gi * 128 + d];
    const float sz = z / (1.f + expf(-z));

    const float yv = c * (1.f / sqrtf(var + EPSF)) * norm_w[d] * sz;
    const size_t idx = (size_t)t * VAL_DIM + hv * 128 + d;
    __nv_bfloat16 h = __float2bfloat16(yv);
    g_y_hi[idx] = h;
    g_y_lo[idx] = __float2bfloat16(yv - __bfloat162float(h));
}

// ---------------- launch ------------------------------------------------------
extern "C" void kernel_launch(void* const* d_in, const int* in_sizes, int n_in,
                              void* d_out, int out_size)
{
    const float* hs      = (const float*)d_in[0];
    const float* w_in    = (const float*)d_in[1];
    const float* conv_w  = (const float*)d_in[2];
    const float* A_log   = (const float*)d_in[3];
    const float* dt_bias = (const float*)d_in[4];
    const float* norm_w  = (const float*)d_in[5];
    const float* w_out   = (const float*)d_in[6];
    float* out = (float*)d_out;

    static bool attr_set = false;
    if (!attr_set) {
        cudaFuncSetAttribute(hgemm_split,
                             cudaFuncAttributeMaxDynamicSharedMemorySize, GEMM_SMEM);
        attr_set = true;
    }

    float *proj_p = nullptr;
    __nv_bfloat16 *hs_hi, *hs_lo, *win_hi, *win_lo, *wout_hi, *wout_lo, *y_hi, *y_lo;
    cudaGetSymbolAddress((void**)&proj_p,  g_proj);
    cudaGetSymbolAddress((void**)&hs_hi,   g_hs_hi);
    cudaGetSymbolAddress((void**)&hs_lo,   g_hs_lo);
    cudaGetSymbolAddress((void**)&win_hi,  g_win_hi);
    cudaGetSymbolAddress((void**)&win_lo,  g_win_lo);
    cudaGetSymbolAddress((void**)&wout_hi, g_wout_hi);
    cudaGetSymbolAddress((void**)&wout_lo, g_wout_lo);
    cudaGetSymbolAddress((void**)&y_hi,    g_y_hi);
    cudaGetSymbolAddress((void**)&y_lo,    g_y_lo);

    // 0. split inputs to bf16 hi/lo
    {
        int n4 = LSEQ * HDIM / 4;
        split_kernel<<<(n4 + 255) / 256, 256>>>((const float4*)hs, hs_hi, hs_lo, n4);
        n4 = HDIM * NPROJ / 4;
        split_kernel<<<(n4 + 255) / 256, 256>>>((const float4*)w_in, win_hi, win_lo, n4);
        n4 = VAL_DIM * HDIM / 4;
        split_kernel<<<(n4 + 255) / 256, 256>>>((const float4*)w_out, wout_hi, wout_lo, n4);
    }

    // 1. in_proj GEMM
    hgemm_split<<<dim3((NPROJ + BN - 1) / BN, LSEQ / BM), 256, GEMM_SMEM>>>(
        hs_hi, hs_lo, win_hi, win_lo, proj_p, LSEQ, NPROJ, HDIM);

    // 2. conv + silu
    conv_silu_kernel<<<(LSEQ * CONV_DIM + 255) / 256, 256>>>(conv_w);

    // 3. beta / g
    gb_kernel<<<(LSEQ * HVN + 255) / 256, 256>>>(A_log, dt_bias);

    // 4. q/k l2norm
    qknorm_kernel<<<dim3(LSEQ, 32), 128>>>();

    // 5. recurrence
    scan_kernel2<<<HVN * 4, 128>>>();

    // 6. gated rmsnorm * silu(z) -> split y
    gated_norm_kernel<<<dim3(LSEQ, HVN), 128>>>(norm_w);

    // 7. out_proj GEMM
    hgemm_split<<<dim3(HDIM / BN, LSEQ / BM), 256, GEMM_SMEM>>>(
        y_hi, y_lo, wout_hi, wout_lo, out, LSEQ, HDIM, VAL_DIM);
}

// round 6
// speedup vs baseline: 1.3639x; 1.3639x over previous
#include <cuda_runtime.h>
#include <cuda_bf16.h>
#include <math.h>

#define LSEQ 4096
#define HDIM 2048
#define HKN  16
#define HVN  32
#define KEY_DIM  2048
#define VAL_DIM  4096
#define CONV_DIM 8192
#define NPROJ    12352
#define QKVZ_DIM 12288
#define EPSF 1e-6f

// ---------------- scratch (device globals; no runtime allocation) ------------
__device__ float g_proj [LSEQ * (size_t)NPROJ];
__device__ float g_mixed[LSEQ * (size_t)CONV_DIM];
__device__ float g_qn   [LSEQ * (size_t)KEY_DIM];
__device__ float g_kn   [LSEQ * (size_t)KEY_DIM];
__device__ float g_g    [LSEQ * HVN];
__device__ float g_beta [LSEQ * HVN];
__device__ float g_core [LSEQ * (size_t)VAL_DIM];

__device__ __nv_bfloat16 g_hs_hi [LSEQ * (size_t)HDIM];
__device__ __nv_bfloat16 g_hs_lo [LSEQ * (size_t)HDIM];
__device__ __nv_bfloat16 g_win_hi[(size_t)HDIM * NPROJ];
__device__ __nv_bfloat16 g_win_lo[(size_t)HDIM * NPROJ];
__device__ __nv_bfloat16 g_wout_hi[(size_t)VAL_DIM * HDIM];
__device__ __nv_bfloat16 g_wout_lo[(size_t)VAL_DIM * HDIM];
__device__ __nv_bfloat16 g_y_hi [LSEQ * (size_t)VAL_DIM];
__device__ __nv_bfloat16 g_y_lo [LSEQ * (size_t)VAL_DIM];

// ---------------- helpers ----------------------------------------------------
__device__ __forceinline__ unsigned sptr(const void* p) {
    return (unsigned)__cvta_generic_to_shared(p);
}
__device__ __forceinline__ void ldsm4(unsigned &r0, unsigned &r1, unsigned &r2, unsigned &r3, unsigned a) {
    asm volatile("ldmatrix.sync.aligned.m8n8.x4.shared.b16 {%0,%1,%2,%3},[%4];"
                 : "=r"(r0), "=r"(r1), "=r"(r2), "=r"(r3) : "r"(a));
}
__device__ __forceinline__ void ldsm4t(unsigned &r0, unsigned &r1, unsigned &r2, unsigned &r3, unsigned a) {
    asm volatile("ldmatrix.sync.aligned.m8n8.x4.trans.shared.b16 {%0,%1,%2,%3},[%4];"
                 : "=r"(r0), "=r"(r1), "=r"(r2), "=r"(r3) : "r"(a));
}
__device__ __forceinline__ void mma_bf16(float* c, const unsigned* a, const unsigned* b) {
    asm volatile("mma.sync.aligned.m16n8k16.row.col.f32.bf16.bf16.f32 "
                 "{%0,%1,%2,%3},{%4,%5,%6,%7},{%8,%9},{%0,%1,%2,%3};"
                 : "+f"(c[0]), "+f"(c[1]), "+f"(c[2]), "+f"(c[3])
                 : "r"(a[0]), "r"(a[1]), "r"(a[2]), "r"(a[3]), "r"(b[0]), "r"(b[1]));
}
__device__ __forceinline__ void cpa16(unsigned d, const void* s, int sz) {
    asm volatile("cp.async.cg.shared.global [%0],[%1],16,%2;" :: "r"(d), "l"(s), "r"(sz));
}

// ---------------- fp32 -> (bf16 hi, bf16 lo) split ---------------------------
__global__ void split_kernel(const float4* __restrict__ x,
                             __nv_bfloat16* __restrict__ hi,
                             __nv_bfloat16* __restrict__ lo, int n4)
{
    int i = blockIdx.x * blockDim.x + threadIdx.x;
    if (i >= n4) return;
    float4 v = x[i];
    float f[4] = {v.x, v.y, v.z, v.w};
    __nv_bfloat16 h[4], l[4];
#pragma unroll
    for (int j = 0; j < 4; j++) {
        h[j] = __float2bfloat16(f[j]);
        l[j] = __float2bfloat16(f[j] - __bfloat162float(h[j]));
    }
    ((__nv_bfloat162*)hi)[2*i]   = __nv_bfloat162(h[0], h[1]);
    ((__nv_bfloat162*)hi)[2*i+1] = __nv_bfloat162(h[2], h[3]);
    ((__nv_bfloat162*)lo)[2*i]   = __nv_bfloat162(l[0], l[1]);
    ((__nv_bfloat162*)lo)[2*i+1] = __nv_bfloat162(l[2], l[3]);
}

// ---------------- bf16-split tensor-core GEMM (mma.sync, 2-stage) ------------
// C[M,N] = (Ahi+Alo)[M,K] @ (Bhi+Blo)[K,N], fp32 acc, 3 passes (pass-outer).
// BM=128, BN=128, BK=32, 256 threads, 2 CTAs/SM.
#define BM 128
#define BN 128
#define BK 32
#define A_ST 40
#define B_ST 136
#define A_TILE (BM * A_ST)
#define B_TILE (BK * B_ST)
#define GEMM_SMEM ((4 * A_TILE + 4 * B_TILE) * 2)

__global__ __launch_bounds__(256, 2) void hgemm_split(
    const __nv_bfloat16* __restrict__ Ahi, const __nv_bfloat16* __restrict__ Alo,
    const __nv_bfloat16* __restrict__ Bhi, const __nv_bfloat16* __restrict__ Blo,
    float* __restrict__ C, int M, int N, int K)
{
    extern __shared__ __nv_bfloat16 sm[];
    __nv_bfloat16* sAh = sm;
    __nv_bfloat16* sAl = sm + 2 * A_TILE;
    __nv_bfloat16* sBh = sm + 4 * A_TILE;
    __nv_bfloat16* sBl = sm + 4 * A_TILE + 2 * B_TILE;

    const int tid  = threadIdx.x;
    const int lane = tid & 31;
    const int wid  = tid >> 5;
    const int wm   = (wid & 1) * 64;
    const int wn   = (wid >> 1) * 32;

    const int rowBase = blockIdx.y * BM;
    const int colBase = blockIdx.x * BN;

    float acc[4][4][4];
#pragma unroll
    for (int a = 0; a < 4; a++)
#pragma unroll
        for (int b = 0; b < 4; b++)
#pragma unroll
            for (int c = 0; c < 4; c++) acc[a][b][c] = 0.f;

    const int numTiles = K / BK;

    auto issue_tile = [&](int t, int buf) {
        const int k0 = t * BK;
#pragma unroll
        for (int i = 0; i < 2; i++) {
            int c  = tid + i * 256;
            int r  = c >> 2;
            int kc = (c & 3) * 8;
            size_t goff = (size_t)(rowBase + r) * K + k0 + kc;
            int soff = buf * A_TILE + r * A_ST + kc;
            cpa16(sptr(sAh + soff), Ahi + goff, 16);
            cpa16(sptr(sAl + soff), Alo + goff, 16);
        }
#pragma unroll
        for (int i = 0; i < 2; i++) {
            int c  = tid + i * 256;
            int r  = c >> 4;
            int nc = (c & 15) * 8;
            int col = colBase + nc;
            int sz  = (col < N) ? 16 : 0;
            size_t goff = sz ? ((size_t)(k0 + r) * N + col) : 0;
            int soff = buf * B_TILE + r * B_ST + nc;
            cpa16(sptr(sBh + soff), Bhi + goff, sz);
            cpa16(sptr(sBl + soff), Blo + goff, sz);
        }
        asm volatile("cp.async.commit_group;");
    };

    issue_tile(0, 0);

    int buf = 0;
    for (int t = 0; t < numTiles; t++) {
        if (t + 1 < numTiles) issue_tile(t + 1, buf ^ 1);
        else                  asm volatile("cp.async.commit_group;");
        asm volatile("cp.async.wait_group 1;");
        __syncthreads();

        const __nv_bfloat16* pAh = sAh + buf * A_TILE;
        const __nv_bfloat16* pAl = sAl + buf * A_TILE;
        const __nv_bfloat16* pBh = sBh + buf * B_TILE;
        const __nv_bfloat16* pBl = sBl + buf * B_TILE;

#pragma unroll
        for (int ks = 0; ks < 2; ks++) {
            unsigned ah[4][4], al[4][4], bh[4][2], bl[4][2];
            const int ar = lane & 15;
            const int ac = ks * 16 + (lane >> 4) * 8;
#pragma unroll
            for (int mt = 0; mt < 4; mt++) {
                unsigned ad = sptr(pAh + (wm + mt * 16 + ar) * A_ST + ac);
                ldsm4(ah[mt][0], ah[mt][1], ah[mt][2], ah[mt][3], ad);
                unsigned ad2 = sptr(pAl + (wm + mt * 16 + ar) * A_ST + ac);
                ldsm4(al[mt][0], al[mt][1], al[mt][2], al[mt][3], ad2);
            }
            const int brow = ks * 16 + (lane & 7) + ((lane & 8) ? 8 : 0);
            const int bcsel = ((lane >> 4) & 1) * 8;
#pragma unroll
            for (int pr = 0; pr < 2; pr++) {
                int bc = wn + pr * 16 + bcsel;
                unsigned bd = sptr(pBh + brow * B_ST + bc);
                ldsm4t(bh[pr*2][0], bh[pr*2][1], bh[pr*2+1][0], bh[pr*2+1][1], bd);
                unsigned bd2 = sptr(pBl + brow * B_ST + bc);
                ldsm4t(bl[pr*2][0], bl[pr*2][1], bl[pr*2+1][0], bl[pr*2+1][1], bd2);
            }
            // pass-outer ordering: each acc reused every 16 MMAs (no RAW chains)
#pragma unroll
            for (int mt = 0; mt < 4; mt++)
#pragma unroll
                for (int nt = 0; nt < 4; nt++)
                    mma_bf16(acc[mt][nt], ah[mt], bh[nt]);
#pragma unroll
            for (int mt = 0; mt < 4; mt++)
#pragma unroll
                for (int nt = 0; nt < 4; nt++)
                    mma_bf16(acc[mt][nt], ah[mt], bl[nt]);
#pragma unroll
            for (int mt = 0; mt < 4; mt++)
#pragma unroll
                for (int nt = 0; nt < 4; nt++)
                    mma_bf16(acc[mt][nt], al[mt], bh[nt]);
        }
        __syncthreads();
        buf ^= 1;
    }

#pragma unroll
    for (int mt = 0; mt < 4; mt++)
#pragma unroll
        for (int nt = 0; nt < 4; nt++) {
            int row = rowBase + wm + mt * 16 + (lane >> 2);
            int col = colBase + wn + nt * 8 + (lane & 3) * 2;
            if (col < N) {
                float2 v0 = make_float2(acc[mt][nt][0], acc[mt][nt][1]);
                float2 v1 = make_float2(acc[mt][nt][2], acc[mt][nt][3]);
                *(float2*)(C + (size_t)row * N + col)       = v0;
                *(float2*)(C + (size_t)(row + 8) * N + col) = v1;
            }
        }
}

// ---------------- causal conv(K=4) + SiLU ------------------------------------
__global__ void conv_silu_kernel(const float* __restrict__ conv_w)
{
    const int idx = blockIdx.x * blockDim.x + threadIdx.x;
    if (idx >= LSEQ * CONV_DIM) return;
    const int t = idx / CONV_DIM;
    const int c = idx - t * CONV_DIM;

    int col;
    if (c < KEY_DIM) {
        col = (c >> 7) * 768 + (c & 127);
    } else if (c < 2 * KEY_DIM) {
        const int cc = c - KEY_DIM;
        col = (cc >> 7) * 768 + 128 + (cc & 127);
    } else {
        const int cc = c - 2 * KEY_DIM;
        col = (cc >> 8) * 768 + 256 + (cc & 255);
    }

    float accv = 0.f;
#pragma unroll
    for (int j = 0; j < 4; j++) {
        const int tt = t - 3 + j;
        if (tt >= 0)
            accv = fmaf(conv_w[c * 4 + j], g_proj[(size_t)tt * NPROJ + col], accv);
    }
    g_mixed[idx] = accv / (1.f + expf(-accv));
}

// ---------------- beta / g activations ---------------------------------------
__global__ void gb_kernel(const float* __restrict__ A_log,
                          const float* __restrict__ dt_bias)
{
    const int i = blockIdx.x * blockDim.x + threadIdx.x;
    if (i >= LSEQ * HVN) return;
    const int t  = i >> 5;
    const int hv = i & 31;
    const int hk = hv >> 1;
    const int gi = hv & 1;
    const float* row = g_proj + (size_t)t * NPROJ + QKVZ_DIM + hk * 4;
    const float b = row[gi];
    const float a = row[2 + gi];
    g_beta[i] = 1.f / (1.f + expf(-b));
    const float x  = a + dt_bias[hv];
    const float sp = (x > 20.f) ? x : log1pf(expf(x));
    g_g[i] = -expf(A_log[hv]) * sp;
}

// ---------------- q/k L2 normalization ---------------------------------------
__global__ __launch_bounds__(128) void qknorm_kernel()
{
    const int t = blockIdx.x;
    const int h = blockIdx.y;
    const int d = threadIdx.x;
    const bool isQ = h < HKN;
    const int hk = isQ ? h : h - HKN;

    const float v = g_mixed[(size_t)t * CONV_DIM + (isQ ? 0 : KEY_DIM) + hk * 128 + d];

    __shared__ float red[128];
    red[d] = v * v;
    __syncthreads();
    for (int s = 64; s > 0; s >>= 1) {
        if (d < s) red[d] += red[d + s];
        __syncthreads();
    }
    float scale = 1.f / sqrtf(red[0] + EPSF);
    if (isQ) scale *= 0.08838834764831845f;
    const float outv = v * scale;
    if (isQ) g_qn[(size_t)t * KEY_DIM + hk * 128 + d] = outv;
    else     g_kn[(size_t)t * KEY_DIM + hk * 128 + d] = outv;
}

// ---------------- gated delta recurrence (128 blocks, quad row-split) --------
__global__ __launch_bounds__(128, 1) void scan_kernel2()
{
    const int hv = blockIdx.x >> 2;
    const int cg = blockIdx.x & 3;
    const int tid = threadIdx.x;
    const int j  = tid >> 2;
    const int r  = tid & 3;
    const int col = cg * 32 + j;
    const int hk = hv >> 1;

    float S[32];
#pragma unroll
    for (int i = 0; i < 32; i++) S[i] = 0.f;

    __shared__ float2 skq[2][4 * 33];

    const float* kb = g_kn + hk * 128;
    const float* qb = g_qn + hk * 128;
    const float* vb = g_mixed + 2 * KEY_DIM + hv * 128 + col;
    const int sidx = (tid >> 5) * 33 + (tid & 31);

    float2 kq = make_float2(kb[tid], qb[tid]);
    float vv = vb[0];
    float gg = g_g[hv];
    float bb = g_beta[hv];
    skq[0][sidx] = kq;
    __syncthreads();

    for (int t = 0; t < LSEQ; t++) {
        const int buf = t & 1;
        float2 kq_n; float vv_n = 0.f, gg_n = 0.f, bb_n = 0.f;
        if (t + 1 < LSEQ) {
            kq_n = make_float2(kb[(size_t)(t + 1) * KEY_DIM + tid],
                               qb[(size_t)(t + 1) * KEY_DIM + tid]);
            vv_n = vb[(size_t)(t + 1) * CONV_DIM];
            gg_n = g_g[(t + 1) * HVN + hv];
            bb_n = g_beta[(t + 1) * HVN + hv];
        }

        const float eg = expf(gg);
        const float2* kqrow = &skq[buf][r * 33];

        float ks = 0.f;
#pragma unroll
        for (int i = 0; i < 32; i++) {
            S[i] *= eg;
            ks = fmaf(kqrow[i].x, S[i], ks);
        }
        ks += __shfl_xor_sync(0xffffffffu, ks, 1);
        ks += __shfl_xor_sync(0xffffffffu, ks, 2);
        const float delta = (vv - ks) * bb;

        float o = 0.f;
#pragma unroll
        for (int i = 0; i < 32; i++) {
            S[i] = fmaf(kqrow[i].x, delta, S[i]);
            o = fmaf(kqrow[i].y, S[i], o);
        }
        o += __shfl_xor_sync(0xffffffffu, o, 1);
        o += __shfl_xor_sync(0xffffffffu, o, 2);
        if (r == 0)
            g_core[(size_t)t * VAL_DIM + hv * 128 + col] = o;

        if (t + 1 < LSEQ) {
            skq[buf ^ 1][sidx] = kq_n;
            vv = vv_n; gg = gg_n; bb = bb_n;
        }
        __syncthreads();
    }
}

// ---------------- gated RMSNorm * silu(z), writes split bf16 -----------------
__global__ __launch_bounds__(128) void gated_norm_kernel(const float* __restrict__ norm_w)
{
    const int t  = blockIdx.x;
    const int hv = blockIdx.y;
    const int d  = threadIdx.x;
    const int hk = hv >> 1;
    const int gi = hv & 1;

    const float c = g_core[(size_t)t * VAL_DIM + hv * 128 + d];

    __shared__ float red[128];
    red[d] = c * c;
    __syncthreads();
    for (int s = 64; s > 0; s >>= 1) {
        if (d < s) red[d] += red[d + s];
        __syncthreads();
    }
    const float var = red[0] * (1.f / 128.f);

    const float z  = g_proj[(size_t)t * NPROJ + hk * 768 + 512 + gi * 128 + d];
    const float sz = z / (1.f + expf(-z));

    const float yv = c * (1.f / sqrtf(var + EPSF)) * norm_w[d] * sz;
    const size_t idx = (size_t)t * VAL_DIM + hv * 128 + d;
    __nv_bfloat16 h = __float2bfloat16(yv);
    g_y_hi[idx] = h;
    g_y_lo[idx] = __float2bfloat16(yv - __bfloat162float(h));
}

// ---------------- launch ------------------------------------------------------
extern "C" void kernel_launch(void* const* d_in, const int* in_sizes, int n_in,
                              void* d_out, int out_size)
{
    const float* hs      = (const float*)d_in[0];
    const float* w_in    = (const float*)d_in[1];
    const float* conv_w  = (const float*)d_in[2];
    const float* A_log   = (const float*)d_in[3];
    const float* dt_bias = (const float*)d_in[4];
    const float* norm_w  = (const float*)d_in[5];
    const float* w_out   = (const float*)d_in[6];
    float* out = (float*)d_out;

    static bool attr_set = false;
    if (!attr_set) {
        cudaFuncSetAttribute(hgemm_split,
                             cudaFuncAttributeMaxDynamicSharedMemorySize, GEMM_SMEM);
        attr_set = true;
    }

    float *proj_p = nullptr;
    __nv_bfloat16 *hs_hi, *hs_lo, *win_hi, *win_lo, *wout_hi, *wout_lo, *y_hi, *y_lo;
    cudaGetSymbolAddress((void**)&proj_p,  g_proj);
    cudaGetSymbolAddress((void**)&hs_hi,   g_hs_hi);
    cudaGetSymbolAddress((void**)&hs_lo,   g_hs_lo);
    cudaGetSymbolAddress((void**)&win_hi,  g_win_hi);
    cudaGetSymbolAddress((void**)&win_lo,  g_win_lo);
    cudaGetSymbolAddress((void**)&wout_hi, g_wout_hi);
    cudaGetSymbolAddress((void**)&wout_lo, g_wout_lo);
    cudaGetSymbolAddress((void**)&y_hi,    g_y_hi);
    cudaGetSymbolAddress((void**)&y_lo,    g_y_lo);

    // 0. split inputs to bf16 hi/lo
    {
        int n4 = LSEQ * HDIM / 4;
        split_kernel<<<(n4 + 255) / 256, 256>>>((const float4*)hs, hs_hi, hs_lo, n4);
        n4 = HDIM * NPROJ / 4;
        split_kernel<<<(n4 + 255) / 256, 256>>>((const float4*)w_in, win_hi, win_lo, n4);
        n4 = VAL_DIM * HDIM / 4;
        split_kernel<<<(n4 + 255) / 256, 256>>>((const float4*)w_out, wout_hi, wout_lo, n4);
    }

    // 1. in_proj GEMM
    hgemm_split<<<dim3((NPROJ + BN - 1) / BN, LSEQ / BM), 256, GEMM_SMEM>>>(
        hs_hi, hs_lo, win_hi, win_lo, proj_p, LSEQ, NPROJ, HDIM);

    // 2. conv + silu
    conv_silu_kernel<<<(LSEQ * CONV_DIM + 255) / 256, 256>>>(conv_w);

    // 3. beta / g
    gb_kernel<<<(LSEQ * HVN + 255) / 256, 256>>>(A_log, dt_bias);

    // 4. q/k l2norm
    qknorm_kernel<<<dim3(LSEQ, 32), 128>>>();

    // 5. recurrence
    scan_kernel2<<<HVN * 4, 128>>>();

    // 6. gated rmsnorm * silu(z) -> split y
    gated_norm_kernel<<<dim3(LSEQ, HVN), 128>>>(norm_w);

    // 7. out_proj GEMM
    hgemm_split<<<dim3(HDIM / BN, LSEQ / BM), 256, GEMM_SMEM>>>(
        y_hi, y_lo, wout_hi, wout_lo, out, LSEQ, HDIM, VAL_DIM);
}

// round 7
// speedup vs baseline: 1.6727x; 1.2264x over previous
#include <cuda_runtime.h>
#include <cuda_bf16.h>
#include <math.h>

#define LSEQ 4096
#define HDIM 2048
#define HKN  16
#define HVN  32
#define KEY_DIM  2048
#define VAL_DIM  4096
#define CONV_DIM 8192
#define NPROJ    12352
#define QKVZ_DIM 12288
#define EPSF 1e-6f

// ---------------- scratch (device globals; no runtime allocation) ------------
__device__ float g_proj [LSEQ * (size_t)NPROJ];
__device__ float g_mixed[LSEQ * (size_t)CONV_DIM];
__device__ float g_qn   [LSEQ * (size_t)KEY_DIM];
__device__ float g_kn   [LSEQ * (size_t)KEY_DIM];
__device__ float g_g    [LSEQ * HVN];
__device__ float g_beta [LSEQ * HVN];
__device__ float g_core [LSEQ * (size_t)VAL_DIM];

__device__ __nv_bfloat16 g_hs_hi [LSEQ * (size_t)HDIM];
__device__ __nv_bfloat16 g_hs_lo [LSEQ * (size_t)HDIM];
__device__ __nv_bfloat16 g_win_hi[(size_t)HDIM * NPROJ];
__device__ __nv_bfloat16 g_win_lo[(size_t)HDIM * NPROJ];
__device__ __nv_bfloat16 g_wout_hi[(size_t)VAL_DIM * HDIM];
__device__ __nv_bfloat16 g_wout_lo[(size_t)VAL_DIM * HDIM];
__device__ __nv_bfloat16 g_y_hi [LSEQ * (size_t)VAL_DIM];
__device__ __nv_bfloat16 g_y_lo [LSEQ * (size_t)VAL_DIM];

// ---------------- helpers ----------------------------------------------------
__device__ __forceinline__ unsigned sptr(const void* p) {
    return (unsigned)__cvta_generic_to_shared(p);
}
__device__ __forceinline__ void ldsm4(unsigned &r0, unsigned &r1, unsigned &r2, unsigned &r3, unsigned a) {
    asm volatile("ldmatrix.sync.aligned.m8n8.x4.shared.b16 {%0,%1,%2,%3},[%4];"
                 : "=r"(r0), "=r"(r1), "=r"(r2), "=r"(r3) : "r"(a));
}
__device__ __forceinline__ void ldsm4t(unsigned &r0, unsigned &r1, unsigned &r2, unsigned &r3, unsigned a) {
    asm volatile("ldmatrix.sync.aligned.m8n8.x4.trans.shared.b16 {%0,%1,%2,%3},[%4];"
                 : "=r"(r0), "=r"(r1), "=r"(r2), "=r"(r3) : "r"(a));
}
__device__ __forceinline__ void mma_bf16(float* c, const unsigned* a, const unsigned* b) {
    asm volatile("mma.sync.aligned.m16n8k16.row.col.f32.bf16.bf16.f32 "
                 "{%0,%1,%2,%3},{%4,%5,%6,%7},{%8,%9},{%0,%1,%2,%3};"
                 : "+f"(c[0]), "+f"(c[1]), "+f"(c[2]), "+f"(c[3])
                 : "r"(a[0]), "r"(a[1]), "r"(a[2]), "r"(a[3]), "r"(b[0]), "r"(b[1]));
}
__device__ __forceinline__ void cpa16(unsigned d, const void* s, int sz) {
    asm volatile("cp.async.cg.shared.global [%0],[%1],16,%2;" :: "r"(d), "l"(s), "r"(sz));
}

// ---------------- fp32 -> (bf16 hi, bf16 lo) split ---------------------------
__global__ void split_kernel(const float4* __restrict__ x,
                             __nv_bfloat16* __restrict__ hi,
                             __nv_bfloat16* __restrict__ lo, int n4)
{
    int i = blockIdx.x * blockDim.x + threadIdx.x;
    if (i >= n4) return;
    float4 v = x[i];
    float f[4] = {v.x, v.y, v.z, v.w};
    __nv_bfloat16 h[4], l[4];
#pragma unroll
    for (int j = 0; j < 4; j++) {
        h[j] = __float2bfloat16(f[j]);
        l[j] = __float2bfloat16(f[j] - __bfloat162float(h[j]));
    }
    ((__nv_bfloat162*)hi)[2*i]   = __nv_bfloat162(h[0], h[1]);
    ((__nv_bfloat162*)hi)[2*i+1] = __nv_bfloat162(h[2], h[3]);
    ((__nv_bfloat162*)lo)[2*i]   = __nv_bfloat162(l[0], l[1]);
    ((__nv_bfloat162*)lo)[2*i+1] = __nv_bfloat162(l[2], l[3]);
}

// ---------------- bf16-split tensor-core GEMM (round-4 config) ---------------
#define BM 128
#define BN 128
#define BK 32
#define A_ST 40
#define B_ST 136
#define A_TILE (BM * A_ST)
#define B_TILE (BK * B_ST)
#define GEMM_SMEM ((4 * A_TILE + 4 * B_TILE) * 2)

__global__ __launch_bounds__(256, 2) void hgemm_split(
    const __nv_bfloat16* __restrict__ Ahi, const __nv_bfloat16* __restrict__ Alo,
    const __nv_bfloat16* __restrict__ Bhi, const __nv_bfloat16* __restrict__ Blo,
    float* __restrict__ C, int M, int N, int K)
{
    extern __shared__ __nv_bfloat16 sm[];
    __nv_bfloat16* sAh = sm;
    __nv_bfloat16* sAl = sm + 2 * A_TILE;
    __nv_bfloat16* sBh = sm + 4 * A_TILE;
    __nv_bfloat16* sBl = sm + 4 * A_TILE + 2 * B_TILE;

    const int tid  = threadIdx.x;
    const int lane = tid & 31;
    const int wid  = tid >> 5;
    const int wm   = (wid & 1) * 64;
    const int wn   = (wid >> 1) * 32;

    const int rowBase = blockIdx.y * BM;
    const int colBase = blockIdx.x * BN;

    float acc[4][4][4];
#pragma unroll
    for (int a = 0; a < 4; a++)
#pragma unroll
        for (int b = 0; b < 4; b++)
#pragma unroll
            for (int c = 0; c < 4; c++) acc[a][b][c] = 0.f;

    const int numTiles = K / BK;

    auto issue_tile = [&](int t, int buf) {
        const int k0 = t * BK;
#pragma unroll
        for (int i = 0; i < 2; i++) {
            int c  = tid + i * 256;
            int r  = c >> 2;
            int kc = (c & 3) * 8;
            size_t goff = (size_t)(rowBase + r) * K + k0 + kc;
            int soff = buf * A_TILE + r * A_ST + kc;
            cpa16(sptr(sAh + soff), Ahi + goff, 16);
            cpa16(sptr(sAl + soff), Alo + goff, 16);
        }
#pragma unroll
        for (int i = 0; i < 2; i++) {
            int c  = tid + i * 256;
            int r  = c >> 4;
            int nc = (c & 15) * 8;
            int col = colBase + nc;
            int sz  = (col < N) ? 16 : 0;
            size_t goff = sz ? ((size_t)(k0 + r) * N + col) : 0;
            int soff = buf * B_TILE + r * B_ST + nc;
            cpa16(sptr(sBh + soff), Bhi + goff, sz);
            cpa16(sptr(sBl + soff), Blo + goff, sz);
        }
        asm volatile("cp.async.commit_group;");
    };

    issue_tile(0, 0);

    int buf = 0;
    for (int t = 0; t < numTiles; t++) {
        if (t + 1 < numTiles) issue_tile(t + 1, buf ^ 1);
        else                  asm volatile("cp.async.commit_group;");
        asm volatile("cp.async.wait_group 1;");
        __syncthreads();

        const __nv_bfloat16* pAh = sAh + buf * A_TILE;
        const __nv_bfloat16* pAl = sAl + buf * A_TILE;
        const __nv_bfloat16* pBh = sBh + buf * B_TILE;
        const __nv_bfloat16* pBl = sBl + buf * B_TILE;

#pragma unroll
        for (int ks = 0; ks < 2; ks++) {
            unsigned ah[4][4], al[4][4], bh[4][2], bl[4][2];
            const int ar = lane & 15;
            const int ac = ks * 16 + (lane >> 4) * 8;
#pragma unroll
            for (int mt = 0; mt < 4; mt++) {
                unsigned ad = sptr(pAh + (wm + mt * 16 + ar) * A_ST + ac);
                ldsm4(ah[mt][0], ah[mt][1], ah[mt][2], ah[mt][3], ad);
                unsigned ad2 = sptr(pAl + (wm + mt * 16 + ar) * A_ST + ac);
                ldsm4(al[mt][0], al[mt][1], al[mt][2], al[mt][3], ad2);
            }
            const int brow = ks * 16 + (lane & 7) + ((lane & 8) ? 8 : 0);
            const int bcsel = ((lane >> 4) & 1) * 8;
#pragma unroll
            for (int pr = 0; pr < 2; pr++) {
                int bc = wn + pr * 16 + bcsel;
                unsigned bd = sptr(pBh + brow * B_ST + bc);
                ldsm4t(bh[pr*2][0], bh[pr*2][1], bh[pr*2+1][0], bh[pr*2+1][1], bd);
                unsigned bd2 = sptr(pBl + brow * B_ST + bc);
                ldsm4t(bl[pr*2][0], bl[pr*2][1], bl[pr*2+1][0], bl[pr*2+1][1], bd2);
            }
#pragma unroll
            for (int mt = 0; mt < 4; mt++)
#pragma unroll
                for (int nt = 0; nt < 4; nt++) {
                    mma_bf16(acc[mt][nt], ah[mt], bh[nt]);
                    mma_bf16(acc[mt][nt], ah[mt], bl[nt]);
                    mma_bf16(acc[mt][nt], al[mt], bh[nt]);
                }
        }
        __syncthreads();
        buf ^= 1;
    }

#pragma unroll
    for (int mt = 0; mt < 4; mt++)
#pragma unroll
        for (int nt = 0; nt < 4; nt++) {
            int row = rowBase + wm + mt * 16 + (lane >> 2);
            int col = colBase + wn + nt * 8 + (lane & 3) * 2;
            if (col < N) {
                float2 v0 = make_float2(acc[mt][nt][0], acc[mt][nt][1]);
                float2 v1 = make_float2(acc[mt][nt][2], acc[mt][nt][3]);
                *(float2*)(C + (size_t)row * N + col)       = v0;
                *(float2*)(C + (size_t)(row + 8) * N + col) = v1;
            }
        }
}

// ---------------- causal conv(K=4) + SiLU ------------------------------------
__global__ void conv_silu_kernel(const float* __restrict__ conv_w)
{
    const int idx = blockIdx.x * blockDim.x + threadIdx.x;
    if (idx >= LSEQ * CONV_DIM) return;
    const int t = idx / CONV_DIM;
    const int c = idx - t * CONV_DIM;

    int col;
    if (c < KEY_DIM) {
        col = (c >> 7) * 768 + (c & 127);
    } else if (c < 2 * KEY_DIM) {
        const int cc = c - KEY_DIM;
        col = (cc >> 7) * 768 + 128 + (cc & 127);
    } else {
        const int cc = c - 2 * KEY_DIM;
        col = (cc >> 8) * 768 + 256 + (cc & 255);
    }

    float accv = 0.f;
#pragma unroll
    for (int j = 0; j < 4; j++) {
        const int tt = t - 3 + j;
        if (tt >= 0)
            accv = fmaf(conv_w[c * 4 + j], g_proj[(size_t)tt * NPROJ + col], accv);
    }
    g_mixed[idx] = accv / (1.f + expf(-accv));
}

// ---------------- beta / g activations ---------------------------------------
__global__ void gb_kernel(const float* __restrict__ A_log,
                          const float* __restrict__ dt_bias)
{
    const int i = blockIdx.x * blockDim.x + threadIdx.x;
    if (i >= LSEQ * HVN) return;
    const int t  = i >> 5;
    const int hv = i & 31;
    const int hk = hv >> 1;
    const int gi = hv & 1;
    const float* row = g_proj + (size_t)t * NPROJ + QKVZ_DIM + hk * 4;
    const float b = row[gi];
    const float a = row[2 + gi];
    g_beta[i] = 1.f / (1.f + expf(-b));
    const float x  = a + dt_bias[hv];
    const float sp = (x > 20.f) ? x : log1pf(expf(x));
    g_g[i] = -expf(A_log[hv]) * sp;
}

// ---------------- q/k L2 normalization ---------------------------------------
__global__ __launch_bounds__(128) void qknorm_kernel()
{
    const int t = blockIdx.x;
    const int h = blockIdx.y;
    const int d = threadIdx.x;
    const bool isQ = h < HKN;
    const int hk = isQ ? h : h - HKN;

    const float v = g_mixed[(size_t)t * CONV_DIM + (isQ ? 0 : KEY_DIM) + hk * 128 + d];

    __shared__ float red[128];
    red[d] = v * v;
    __syncthreads();
    for (int s = 64; s > 0; s >>= 1) {
        if (d < s) red[d] += red[d + s];
        __syncthreads();
    }
    float scale = 1.f / sqrtf(red[0] + EPSF);
    if (isQ) scale *= 0.08838834764831845f;
    const float outv = v * scale;
    if (isQ) g_qn[(size_t)t * KEY_DIM + hk * 128 + d] = outv;
    else     g_kn[(size_t)t * KEY_DIM + hk * 128 + d] = outv;
}

// ---------------- gated delta recurrence (4-way split accumulators) ----------
__global__ __launch_bounds__(128, 1) void scan_kernel2()
{
    const int hv = blockIdx.x >> 2;
    const int cg = blockIdx.x & 3;
    const int tid = threadIdx.x;
    const int j  = tid >> 2;
    const int r  = tid & 3;
    const int col = cg * 32 + j;
    const int hk = hv >> 1;

    float S[32];
#pragma unroll
    for (int i = 0; i < 32; i++) S[i] = 0.f;

    __shared__ float2 skq[2][4 * 33];

    const float* kb = g_kn + hk * 128;
    const float* qb = g_qn + hk * 128;
    const float* vb = g_mixed + 2 * KEY_DIM + hv * 128 + col;
    const int sidx = (tid >> 5) * 33 + (tid & 31);

    float2 kq = make_float2(kb[tid], qb[tid]);
    float vv = vb[0];
    float gg = g_g[hv];
    float bb = g_beta[hv];
    skq[0][sidx] = kq;
    __syncthreads();

    for (int t = 0; t < LSEQ; t++) {
        const int buf = t & 1;
        float2 kq_n; float vv_n = 0.f, gg_n = 0.f, bb_n = 0.f;
        if (t + 1 < LSEQ) {
            kq_n = make_float2(kb[(size_t)(t + 1) * KEY_DIM + tid],
                               qb[(size_t)(t + 1) * KEY_DIM + tid]);
            vv_n = vb[(size_t)(t + 1) * CONV_DIM];
            gg_n = g_g[(t + 1) * HVN + hv];
            bb_n = g_beta[(t + 1) * HVN + hv];
        }

        const float eg = expf(gg);
        const float2* kqrow = &skq[buf][r * 33];

        // 4-way split accumulators: chain depth 8 instead of 32
        float k0 = 0.f, k1 = 0.f, k2 = 0.f, k3 = 0.f;
#pragma unroll
        for (int i = 0; i < 32; i += 4) {
            S[i + 0] *= eg; k0 = fmaf(kqrow[i + 0].x, S[i + 0], k0);
            S[i + 1] *= eg; k1 = fmaf(kqrow[i + 1].x, S[i + 1], k1);
            S[i + 2] *= eg; k2 = fmaf(kqrow[i + 2].x, S[i + 2], k2);
            S[i + 3] *= eg; k3 = fmaf(kqrow[i + 3].x, S[i + 3], k3);
        }
        float ks = (k0 + k1) + (k2 + k3);
        ks += __shfl_xor_sync(0xffffffffu, ks, 1);
        ks += __shfl_xor_sync(0xffffffffu, ks, 2);
        const float delta = (vv - ks) * bb;

        float o0 = 0.f, o1 = 0.f, o2 = 0.f, o3 = 0.f;
#pragma unroll
        for (int i = 0; i < 32; i += 4) {
            float2 a0 = kqrow[i + 0]; S[i + 0] = fmaf(a0.x, delta, S[i + 0]); o0 = fmaf(a0.y, S[i + 0], o0);
            float2 a1 = kqrow[i + 1]; S[i + 1] = fmaf(a1.x, delta, S[i + 1]); o1 = fmaf(a1.y, S[i + 1], o1);
            float2 a2 = kqrow[i + 2]; S[i + 2] = fmaf(a2.x, delta, S[i + 2]); o2 = fmaf(a2.y, S[i + 2], o2);
            float2 a3 = kqrow[i + 3]; S[i + 3] = fmaf(a3.x, delta, S[i + 3]); o3 = fmaf(a3.y, S[i + 3], o3);
        }
        float o = (o0 + o1) + (o2 + o3);
        o += __shfl_xor_sync(0xffffffffu, o, 1);
        o += __shfl_xor_sync(0xffffffffu, o, 2);
        if (r == 0)
            g_core[(size_t)t * VAL_DIM + hv * 128 + col] = o;

        if (t + 1 < LSEQ) {
            skq[buf ^ 1][sidx] = kq_n;
            vv = vv_n; gg = gg_n; bb = bb_n;
        }
        __syncthreads();
    }
}

// ---------------- gated RMSNorm * silu(z), writes split bf16 -----------------
__global__ __launch_bounds__(128) void gated_norm_kernel(const float* __restrict__ norm_w)
{
    const int t  = blockIdx.x;
    const int hv = blockIdx.y;
    const int d  = threadIdx.x;
    const int hk = hv >> 1;
    const int gi = hv & 1;

    const float c = g_core[(size_t)t * VAL_DIM + hv * 128 + d];

    __shared__ float red[128];
    red[d] = c * c;
    __syncthreads();
    for (int s = 64; s > 0; s >>= 1) {
        if (d < s) red[d] += red[d + s];
        __syncthreads();
    }
    const float var = red[0] * (1.f / 128.f);

    const float z  = g_proj[(size_t)t * NPROJ + hk * 768 + 512 + gi * 128 + d];
    const float sz = z / (1.f + expf(-z));

    const float yv = c * (1.f / sqrtf(var + EPSF)) * norm_w[d] * sz;
    const size_t idx = (size_t)t * VAL_DIM + hv * 128 + d;
    __nv_bfloat16 h = __float2bfloat16(yv);
    g_y_hi[idx] = h;
    g_y_lo[idx] = __float2bfloat16(yv - __bfloat162float(h));
}

// ---------------- launch ------------------------------------------------------
extern "C" void kernel_launch(void* const* d_in, const int* in_sizes, int n_in,
                              void* d_out, int out_size)
{
    const float* hs      = (const float*)d_in[0];
    const float* w_in    = (const float*)d_in[1];
    const float* conv_w  = (const float*)d_in[2];
    const float* A_log   = (const float*)d_in[3];
    const float* dt_bias = (const float*)d_in[4];
    const float* norm_w  = (const float*)d_in[5];
    const float* w_out   = (const float*)d_in[6];
    float* out = (float*)d_out;

    static bool attr_set = false;
    if (!attr_set) {
        cudaFuncSetAttribute(hgemm_split,
                             cudaFuncAttributeMaxDynamicSharedMemorySize, GEMM_SMEM);
        attr_set = true;
    }

    float *proj_p = nullptr;
    __nv_bfloat16 *hs_hi, *hs_lo, *win_hi, *win_lo, *wout_hi, *wout_lo, *y_hi, *y_lo;
    cudaGetSymbolAddress((void**)&proj_p,  g_proj);
    cudaGetSymbolAddress((void**)&hs_hi,   g_hs_hi);
    cudaGetSymbolAddress((void**)&hs_lo,   g_hs_lo);
    cudaGetSymbolAddress((void**)&win_hi,  g_win_hi);
    cudaGetSymbolAddress((void**)&win_lo,  g_win_lo);
    cudaGetSymbolAddress((void**)&wout_hi, g_wout_hi);
    cudaGetSymbolAddress((void**)&wout_lo, g_wout_lo);
    cudaGetSymbolAddress((void**)&y_hi,    g_y_hi);
    cudaGetSymbolAddress((void**)&y_lo,    g_y_lo);

    // 0. split inputs to bf16 hi/lo
    {
        int n4 = LSEQ * HDIM / 4;
        split_kernel<<<(n4 + 255) / 256, 256>>>((const float4*)hs, hs_hi, hs_lo, n4);
        n4 = HDIM * NPROJ / 4;
        split_kernel<<<(n4 + 255) / 256, 256>>>((const float4*)w_in, win_hi, win_lo, n4);
        n4 = VAL_DIM * HDIM / 4;
        split_kernel<<<(n4 + 255) / 256, 256>>>((const float4*)w_out, wout_hi, wout_lo, n4);
    }

    // 1. in_proj GEMM
    hgemm_split<<<dim3((NPROJ + BN - 1) / BN, LSEQ / BM), 256, GEMM_SMEM>>>(
        hs_hi, hs_lo, win_hi, win_lo, proj_p, LSEQ, NPROJ, HDIM);

    // 2. conv + silu
    conv_silu_kernel<<<(LSEQ * CONV_DIM + 255) / 256, 256>>>(conv_w);

    // 3. beta / g
    gb_kernel<<<(LSEQ * HVN + 255) / 256, 256>>>(A_log, dt_bias);

    // 4. q/k l2norm
    qknorm_kernel<<<dim3(LSEQ, 32), 128>>>();

    // 5. recurrence
    scan_kernel2<<<HVN * 4, 128>>>();

    // 6. gated rmsnorm * silu(z) -> split y
    gated_norm_kernel<<<dim3(LSEQ, HVN), 128>>>(norm_w);

    // 7. out_proj GEMM
    hgemm_split<<<dim3(HDIM / BN, LSEQ / BM), 256, GEMM_SMEM>>>(
        y_hi, y_lo, wout_hi, wout_lo, out, LSEQ, HDIM, VAL_DIM);
}